// round 4
// baseline (speedup 1.0000x reference)
#include <cuda_runtime.h>
#include <cuda_fp16.h>
#include <cstdint>

#define BATCH 8
#define NN 2048
#define FD 256
#define EPSV 1e-7f
#define NSLOPE 0.2f

// ---------------- device scratch ----------------
static __device__ float g_Wh[BATCH * NN * FD];                 // 16 MB
static __device__ float g_P [BATCH * NN];
static __device__ float g_Q [BATCH * NN];
static __device__ float g_E1[BATCH * NN];
static __device__ float g_E2[BATCH * NN];
static __device__ float g_F1[BATCH * NN];
static __device__ float g_F2[BATCH * NN];
static __device__ float g_D [BATCH * NN];
// bit-plane masks, layout [b][jw (64 words of 32 j)][i (2048)]
static __device__ uint32_t g_B1T[BATCH * 64 * 2048];           // 4 MB
static __device__ uint32_t g_B2T[BATCH * 64 * 2048];           // 4 MB
static __device__ __half g_H1[BATCH * NN * FD];                // (F1/D)*Wh fp16
static __device__ __half g_H2[BATCH * NN * FD];                // (F2/D)*Wh fp16

// ---------------- helpers ----------------
__device__ __forceinline__ unsigned long long pack2(float x, float y) {
    unsigned long long r;
    asm("mov.b64 %0, {%1, %2};" : "=l"(r) : "f"(x), "f"(y));
    return r;
}
__device__ __forceinline__ float2 unpack2(unsigned long long v) {
    float2 r;
    asm("mov.b64 {%0, %1}, %2;" : "=f"(r.x), "=f"(r.y) : "l"(v));
    return r;
}
__device__ __forceinline__ void ffma2(unsigned long long& d,
                                      unsigned long long a,
                                      unsigned long long b) {
    asm("fma.rn.f32x2 %0, %1, %2, %3;" : "=l"(d) : "l"(a), "l"(b), "l"(d));
}
__device__ __forceinline__ uint32_t smem_u32(const void* p) {
    uint32_t a;
    asm("{ .reg .u64 t; cvta.to.shared.u64 t, %1; cvt.u32.u64 %0, t; }" : "=r"(a) : "l"(p));
    return a;
}
__device__ __forceinline__ void cp_async16(uint32_t dst, const void* src) {
    asm volatile("cp.async.cg.shared.global [%0], [%1], 16;" :: "r"(dst), "l"(src));
}
#define CP_COMMIT() asm volatile("cp.async.commit_group;" ::: "memory")

__device__ __forceinline__ void ldsm_x4(uint32_t& r0, uint32_t& r1, uint32_t& r2,
                                        uint32_t& r3, uint32_t addr) {
    asm volatile("ldmatrix.sync.aligned.m8n8.x4.shared.b16 {%0,%1,%2,%3}, [%4];"
                 : "=r"(r0), "=r"(r1), "=r"(r2), "=r"(r3) : "r"(addr));
}
__device__ __forceinline__ void ldsm_x4_t(uint32_t& r0, uint32_t& r1, uint32_t& r2,
                                          uint32_t& r3, uint32_t addr) {
    asm volatile("ldmatrix.sync.aligned.m8n8.x4.trans.shared.b16 {%0,%1,%2,%3}, [%4];"
                 : "=r"(r0), "=r"(r1), "=r"(r2), "=r"(r3) : "r"(addr));
}
__device__ __forceinline__ void mma16816(float* d, const uint32_t* a, uint32_t b0,
                                         uint32_t b1) {
    asm volatile("mma.sync.aligned.m16n8k16.row.col.f32.f16.f16.f32 "
                 "{%0,%1,%2,%3}, {%4,%5,%6,%7}, {%8,%9}, {%0,%1,%2,%3};"
                 : "+f"(d[0]), "+f"(d[1]), "+f"(d[2]), "+f"(d[3])
                 : "r"(a[0]), "r"(a[1]), "r"(a[2]), "r"(a[3]), "r"(b0), "r"(b1));
}

// =====================================================================
// K1: Wh = x @ W  (fp32 f32x2)
// =====================================================================
__global__ __launch_bounds__(256) void k_gemm_wh(const float* __restrict__ x,
                                                 const float* __restrict__ W) {
    __shared__ __align__(16) float Xs[64][32];
    __shared__ __align__(16) float Ws[32][256];
    const int r0 = blockIdx.x * 64;
    const int tid = threadIdx.x, lane = tid & 31, w = tid >> 5;

    unsigned long long acc[8][4];
#pragma unroll
    for (int r = 0; r < 8; r++)
#pragma unroll
        for (int m = 0; m < 4; m++) acc[r][m] = 0ull;

    for (int k0 = 0; k0 < FD; k0 += 32) {
#pragma unroll
        for (int rr = 0; rr < 8; rr++) {
            int e = tid + 256 * rr;
            Xs[e >> 5][e & 31] = x[(r0 + (e >> 5)) * FD + k0 + (e & 31)];
        }
#pragma unroll
        for (int rr = 0; rr < 8; rr++) {
            int e = tid + 256 * rr;
            int j = e >> 6, o4 = e & 63;
            *(float4*)&Ws[j][o4 * 4] = *(const float4*)&W[(k0 + j) * FD + o4 * 4];
        }
        __syncthreads();
#pragma unroll 4
        for (int kk = 0; kk < 32; kk++) {
            unsigned long long cb[8];
#pragma unroll
            for (int r = 0; r < 8; r++) { float c = Xs[8 * w + r][kk]; cb[r] = pack2(c, c); }
            unsigned long long wv[4];
#pragma unroll
            for (int m = 0; m < 4; m++)
                wv[m] = *(const unsigned long long*)&Ws[kk][2 * lane + 64 * m];
#pragma unroll
            for (int r = 0; r < 8; r++)
#pragma unroll
                for (int m = 0; m < 4; m++) ffma2(acc[r][m], cb[r], wv[m]);
        }
        __syncthreads();
    }
#pragma unroll
    for (int r = 0; r < 8; r++)
#pragma unroll
        for (int m = 0; m < 4; m++) {
            float2 v = unpack2(acc[r][m]);
            *(float2*)&g_Wh[(r0 + 8 * w + r) * FD + 2 * lane + 64 * m] = v;
        }
}

// =====================================================================
// K2: attention vectors + zero D
// =====================================================================
__global__ __launch_bounds__(256) void k_attn_vec(const float* __restrict__ aw,
                                                  const float* __restrict__ ab) {
    const int row = blockIdx.x * 8 + (threadIdx.x >> 5);
    const int lane = threadIdx.x & 31;
    const float* wr = g_Wh + row * FD;
    float s1 = 0.f, s2 = 0.f;
#pragma unroll
    for (int m = 0; m < 2; m++) {
        float4 v = *(const float4*)&wr[lane * 8 + m * 4];
        float4 a1 = *(const float4*)&aw[lane * 8 + m * 4];
        float4 a2 = *(const float4*)&aw[FD + lane * 8 + m * 4];
        s1 += v.x * a1.x + v.y * a1.y + v.z * a1.z + v.w * a1.w;
        s2 += v.x * a2.x + v.y * a2.y + v.z * a2.z + v.w * a2.w;
    }
#pragma unroll
    for (int off = 16; off > 0; off >>= 1) {
        s1 += __shfl_xor_sync(0xffffffffu, s1, off);
        s2 += __shfl_xor_sync(0xffffffffu, s2, off);
    }
    if (lane == 0) {
        float P = s1, Q = s2 + ab[0];
        g_P[row] = P; g_Q[row] = Q;
        g_E1[row] = expf(P);          g_E2[row] = expf(NSLOPE * P);
        g_F1[row] = expf(Q);          g_F2[row] = expf(NSLOPE * Q);
        g_D[row] = 0.f;
    }
}

// =====================================================================
// K3: column sums D[b,j] + bit-plane masks via ballot
// grid: (8 j-blocks, 8 b, 8 i-segs), 256 threads (thread = j)
// =====================================================================
__global__ __launch_bounds__(256) void k_colsum(const float* __restrict__ A) {
    const int b = blockIdx.y, jblk = blockIdx.x;
    const int tid = threadIdx.x, lane = tid & 31, wid = tid >> 5;
    const int j = jblk * 256 + tid;
    const int ibase = blockIdx.z * 256;
    __shared__ float sP[256], sE1[256], sE2[256];
    __shared__ uint32_t sb1[8][256], sb2[8][256];
    sP [tid] = g_P [b * NN + ibase + tid];
    sE1[tid] = g_E1[b * NN + ibase + tid];
    sE2[tid] = g_E2[b * NN + ibase + tid];
    __syncthreads();
    const float Qj = g_Q[b * NN + j], F1j = g_F1[b * NN + j], F2j = g_F2[b * NN + j];
    const float* Ab = A + (size_t)(b * NN + ibase) * NN + j;
    float acc = 0.f;
#pragma unroll 2
    for (int ii = 0; ii < 256; ii++) {
        float a = Ab[(size_t)ii * NN];
        bool nz = (a != 0.f);
        bool pos = (sP[ii] + Qj > 0.f);
        acc = fmaf(a, pos ? sE1[ii] * F1j : sE2[ii] * F2j, acc);
        uint32_t b1 = __ballot_sync(0xffffffffu, nz && pos);
        uint32_t b2 = __ballot_sync(0xffffffffu, nz && !pos);
        if (lane == 0) { sb1[wid][ii] = b1; sb2[wid][ii] = b2; }
    }
    atomicAdd(&g_D[b * NN + j], acc);
    __syncthreads();
#pragma unroll
    for (int r = 0; r < 8; r++) {
        int idx = tid + 256 * r;
        int jwl = idx >> 8, ii = idx & 255;
        size_t gi = ((size_t)b * 64 + jblk * 8 + jwl) * 2048 + ibase + ii;
        g_B1T[gi] = sb1[jwl][ii];
        g_B2T[gi] = sb2[jwl][ii];
    }
}

// =====================================================================
// K_hprep: H1 = (F1/D)*Wh, H2 = (F2/D)*Wh in fp16
// =====================================================================
__global__ __launch_bounds__(256) void k_hprep() {
    int e4 = blockIdx.x * 256 + threadIdx.x;
    int row = e4 >> 6;
    float inv = 1.f / (g_D[row] + EPSV);
    float r1 = g_F1[row] * inv, r2 = g_F2[row] * inv;
    float4 w = ((const float4*)g_Wh)[e4];
    __half2* h1 = (__half2*)g_H1;
    __half2* h2 = (__half2*)g_H2;
    h1[e4 * 2]     = __floats2half2_rn(w.x * r1, w.y * r1);
    h1[e4 * 2 + 1] = __floats2half2_rn(w.z * r1, w.w * r1);
    h2[e4 * 2]     = __floats2half2_rn(w.x * r2, w.y * r2);
    h2[e4 * 2 + 1] = __floats2half2_rn(w.z * r2, w.w * r2);
}

// =====================================================================
// K4: HMMA mask-GEMM from bit-planes.
// Block 128i x 64o; stage = 32 j; masks expanded from bits into SMEM.
// SMEM/buf (24576B): M1 8K | M2 8K | B1 4K | B2 4K.  2 bufs = 48 KB.
// =====================================================================
#define STG_STRIDE 24576

__device__ __forceinline__ uint32_t m_off(int i, int cq) {
    return (uint32_t)(((i >> 1) << 7) + (((((i & 1) << 2) | cq) ^ ((i >> 1) & 7)) << 4));
}
__device__ __forceinline__ uint32_t b_off(int j, int oc) {
    return (uint32_t)((j << 7) + (((oc ^ (j & 7))) << 4));
}

__global__ __launch_bounds__(256) void k_mma(float* __restrict__ out) {
    __shared__ __align__(128) char smem[2 * STG_STRIDE];
    const uint32_t sb = smem_u32(smem);
    const int tid = threadIdx.x, lane = tid & 31, wid = tid >> 5;
    const int b = blockIdx.z;
    const int i0 = blockIdx.x * 128;
    const int o0 = blockIdx.y * 64;
    const int isub = (wid & 3) * 32;
    const int ocb = (wid >> 2) * 4;

    const int ei = tid & 127, etens = tid >> 7;   // expansion mapping
    const uint32_t* bplane = (etens ? g_B2T : g_B1T) + ((size_t)b * 64) * 2048 + i0 + ei;

    float acc[2][2][4][4];
#pragma unroll
    for (int t = 0; t < 2; t++)
#pragma unroll
        for (int m = 0; m < 2; m++)
#pragma unroll
            for (int n = 0; n < 4; n++)
#pragma unroll
                for (int k = 0; k < 4; k++) acc[t][m][n][k] = 0.f;

    auto issueB = [&](int t, int buf) {
        const int j0 = t * 32;
        uint32_t stg = sb + buf * STG_STRIDE + 16384;
#pragma unroll
        for (int r = 0; r < 2; r++) {
            int idx = tid + 256 * r;
            int tens = idx >> 8, rem = idx & 255;
            int j = rem >> 3, oc = rem & 7;
            const __half* src = (tens ? g_H2 : g_H1) +
                ((size_t)(b * NN + j0 + j) * FD + o0 + oc * 8);
            cp_async16(stg + tens * 4096 + b_off(j, oc), src);
        }
        CP_COMMIT();
    };
    auto expand = [&](uint32_t bits, int buf) {
        uint32_t mbase = sb + buf * STG_STRIDE + etens * 8192;
#pragma unroll
        for (int cq = 0; cq < 4; cq++) {
            uint32_t w = bits >> (cq * 8);
            uint32_t q0 = ((w >> 0) & 1) * 0x3C00u | ((w >> 1) & 1) * 0x3C000000u;
            uint32_t q1 = ((w >> 2) & 1) * 0x3C00u | ((w >> 3) & 1) * 0x3C000000u;
            uint32_t q2 = ((w >> 4) & 1) * 0x3C00u | ((w >> 5) & 1) * 0x3C000000u;
            uint32_t q3 = ((w >> 6) & 1) * 0x3C00u | ((w >> 7) & 1) * 0x3C000000u;
            asm volatile("st.shared.v4.b32 [%0], {%1,%2,%3,%4};"
                         :: "r"(mbase + m_off(ei, cq)), "r"(q0), "r"(q1), "r"(q2), "r"(q3));
        }
    };

    // prologue
    uint32_t cbits = bplane[0];
    issueB(0, 0);
    expand(cbits, 0);
    uint32_t nbits = bplane[2048];

    for (int t = 0; t < 64; t++) {
        const int buf = t & 1;
        __syncthreads();                               // close compute(t-1)
        if (t + 1 < 64) issueB(t + 1, buf ^ 1);
        if (t + 1 < 64) { asm volatile("cp.async.wait_group 1;" ::: "memory"); }
        else            { asm volatile("cp.async.wait_group 0;" ::: "memory"); }
        __syncthreads();                               // publish B(t) + masks(t)

        uint32_t stg = sb + buf * STG_STRIDE;
#pragma unroll
        for (int tens = 0; tens < 2; tens++) {
            uint32_t Bf[4][4];
            uint32_t bb = stg + 16384 + tens * 4096;
#pragma unroll
            for (int jb = 0; jb < 4; jb++) {
                int oblk = lane >> 3;
                int j = jb * 8 + (lane & 7);
                uint32_t addr = bb + b_off(j, ocb + oblk);
                ldsm_x4_t(Bf[jb][0], Bf[jb][1], Bf[jb][2], Bf[jb][3], addr);
            }
            uint32_t mb = stg + tens * 8192;
#pragma unroll
            for (int m = 0; m < 2; m++) {
#pragma unroll
                for (int kt = 0; kt < 2; kt++) {
                    int q = lane >> 3;
                    int i = isub + m * 16 + ((q & 1) << 3) + (lane & 7);
                    int cq = (kt << 1) + (q >> 1);
                    uint32_t a[4];
                    ldsm_x4(a[0], a[1], a[2], a[3], mb + m_off(i, cq));
#pragma unroll
                    for (int nt = 0; nt < 4; nt++)
                        mma16816(acc[tens][m][nt], a, Bf[2 * kt][nt], Bf[2 * kt + 1][nt]);
                }
            }
        }
        // expand masks for stage t+1 into the other buffer (no sync needed:
        // other buffer's previous readers were closed at top-of-loop sync)
        if (t + 1 < 64) expand(nbits, buf ^ 1);
        if (t + 2 < 64) nbits = bplane[(size_t)(t + 2) * 2048];
    }

    // ---- epilogue: out = E1*D1 + E2*D2 ----
    const int gid = lane >> 2, t4 = lane & 3;
#pragma unroll
    for (int m = 0; m < 2; m++) {
        int r0 = i0 + isub + m * 16 + gid;
        int r1 = r0 + 8;
        float e1a = g_E1[b * NN + r0], e2a = g_E2[b * NN + r0];
        float e1b = g_E1[b * NN + r1], e2b = g_E2[b * NN + r1];
#pragma unroll
        for (int nt = 0; nt < 4; nt++) {
            int o = o0 + ocb * 8 + nt * 8 + 2 * t4;
            float2 v0, v1;
            v0.x = e1a * acc[0][m][nt][0] + e2a * acc[1][m][nt][0];
            v0.y = e1a * acc[0][m][nt][1] + e2a * acc[1][m][nt][1];
            v1.x = e1b * acc[0][m][nt][2] + e2b * acc[1][m][nt][2];
            v1.y = e1b * acc[0][m][nt][3] + e2b * acc[1][m][nt][3];
            *(float2*)&out[(size_t)(b * NN + r0) * FD + o] = v0;
            *(float2*)&out[(size_t)(b * NN + r1) * FD + o] = v1;
        }
    }
}

// =====================================================================
extern "C" void kernel_launch(void* const* d_in, const int* in_sizes, int n_in,
                              void* d_out, int out_size) {
    (void)in_sizes; (void)n_in; (void)out_size;
    const float* A  = (const float*)d_in[0];
    const float* x  = (const float*)d_in[1];
    const float* W  = (const float*)d_in[2];
    const float* aw = (const float*)d_in[3];
    const float* ab = (const float*)d_in[4];
    float* out = (float*)d_out;

    k_gemm_wh<<<(BATCH * NN) / 64, 256>>>(x, W);
    k_attn_vec<<<(BATCH * NN) / 8, 256>>>(aw, ab);
    k_colsum<<<dim3(NN / 256, BATCH, NN / 256), 256>>>(A);
    k_hprep<<<(BATCH * NN * FD) / 1024, 256>>>();
    k_mma<<<dim3(NN / 128, FD / 64, BATCH), 256>>>(out);
}

// round 5
// speedup vs baseline: 1.2092x; 1.2092x over previous
#include <cuda_runtime.h>
#include <cuda_fp16.h>
#include <cstdint>

#define BATCH 8
#define NN 2048
#define FD 256
#define EPSV 1e-7f
#define NSLOPE 0.2f

// ---------------- device scratch ----------------
static __device__ float g_Wh[BATCH * NN * FD];                 // 16 MB
static __device__ float g_P [BATCH * NN];
static __device__ float g_Q [BATCH * NN];
static __device__ float g_E1[BATCH * NN];
static __device__ float g_E2[BATCH * NN];
static __device__ float g_F1[BATCH * NN];
static __device__ float g_F2[BATCH * NN];
static __device__ float g_D [BATCH * NN];
static __device__ __half g_M1[(size_t)BATCH * NN * NN];        // 64 MB pos-mask
static __device__ __half g_M2[(size_t)BATCH * NN * NN];        // 64 MB neg-mask
static __device__ __half g_H1[BATCH * NN * FD];                // (F1/D)*Wh fp16
static __device__ __half g_H2[BATCH * NN * FD];                // (F2/D)*Wh fp16

// ---------------- helpers ----------------
__device__ __forceinline__ unsigned long long pack2(float x, float y) {
    unsigned long long r;
    asm("mov.b64 %0, {%1, %2};" : "=l"(r) : "f"(x), "f"(y));
    return r;
}
__device__ __forceinline__ float2 unpack2(unsigned long long v) {
    float2 r;
    asm("mov.b64 {%0, %1}, %2;" : "=f"(r.x), "=f"(r.y) : "l"(v));
    return r;
}
__device__ __forceinline__ void ffma2(unsigned long long& d,
                                      unsigned long long a,
                                      unsigned long long b) {
    asm("fma.rn.f32x2 %0, %1, %2, %3;" : "=l"(d) : "l"(a), "l"(b), "l"(d));
}
__device__ __forceinline__ uint32_t smem_u32(const void* p) {
    uint32_t a;
    asm("{ .reg .u64 t; cvta.to.shared.u64 t, %1; cvt.u32.u64 %0, t; }" : "=r"(a) : "l"(p));
    return a;
}
__device__ __forceinline__ void cp_async16(uint32_t dst, const void* src) {
    asm volatile("cp.async.cg.shared.global [%0], [%1], 16;" :: "r"(dst), "l"(src));
}
#define CP_COMMIT() asm volatile("cp.async.commit_group;" ::: "memory")

__device__ __forceinline__ void ldsm_x4(uint32_t& r0, uint32_t& r1, uint32_t& r2,
                                        uint32_t& r3, uint32_t addr) {
    asm volatile("ldmatrix.sync.aligned.m8n8.x4.shared.b16 {%0,%1,%2,%3}, [%4];"
                 : "=r"(r0), "=r"(r1), "=r"(r2), "=r"(r3) : "r"(addr));
}
__device__ __forceinline__ void ldsm_x4_t(uint32_t& r0, uint32_t& r1, uint32_t& r2,
                                          uint32_t& r3, uint32_t addr) {
    asm volatile("ldmatrix.sync.aligned.m8n8.x4.trans.shared.b16 {%0,%1,%2,%3}, [%4];"
                 : "=r"(r0), "=r"(r1), "=r"(r2), "=r"(r3) : "r"(addr));
}
__device__ __forceinline__ void mma16816(float* d, const uint32_t* a, uint32_t b0,
                                         uint32_t b1) {
    asm volatile("mma.sync.aligned.m16n8k16.row.col.f32.f16.f16.f32 "
                 "{%0,%1,%2,%3}, {%4,%5,%6,%7}, {%8,%9}, {%0,%1,%2,%3};"
                 : "+f"(d[0]), "+f"(d[1]), "+f"(d[2]), "+f"(d[3])
                 : "r"(a[0]), "r"(a[1]), "r"(a[2]), "r"(a[3]), "r"(b0), "r"(b1));
}

// =====================================================================
// K1: Wh = x @ W (fp32 f32x2) + FUSED attention-vector epilogue
// =====================================================================
__global__ __launch_bounds__(256) void k_gemm_wh(const float* __restrict__ x,
                                                 const float* __restrict__ W,
                                                 const float* __restrict__ aw,
                                                 const float* __restrict__ ab) {
    __shared__ __align__(16) float Xs[64][32];
    __shared__ __align__(16) float Ws[32][256];
    const int r0 = blockIdx.x * 64;
    const int tid = threadIdx.x, lane = tid & 31, w = tid >> 5;

    unsigned long long acc[8][4];
#pragma unroll
    for (int r = 0; r < 8; r++)
#pragma unroll
        for (int m = 0; m < 4; m++) acc[r][m] = 0ull;

    for (int k0 = 0; k0 < FD; k0 += 32) {
#pragma unroll
        for (int rr = 0; rr < 8; rr++) {
            int e = tid + 256 * rr;
            Xs[e >> 5][e & 31] = x[(r0 + (e >> 5)) * FD + k0 + (e & 31)];
        }
#pragma unroll
        for (int rr = 0; rr < 8; rr++) {
            int e = tid + 256 * rr;
            int j = e >> 6, o4 = e & 63;
            *(float4*)&Ws[j][o4 * 4] = *(const float4*)&W[(k0 + j) * FD + o4 * 4];
        }
        __syncthreads();
#pragma unroll 4
        for (int kk = 0; kk < 32; kk++) {
            unsigned long long cb[8];
#pragma unroll
            for (int r = 0; r < 8; r++) { float c = Xs[8 * w + r][kk]; cb[r] = pack2(c, c); }
            unsigned long long wv[4];
#pragma unroll
            for (int m = 0; m < 4; m++)
                wv[m] = *(const unsigned long long*)&Ws[kk][2 * lane + 64 * m];
#pragma unroll
            for (int r = 0; r < 8; r++)
#pragma unroll
                for (int m = 0; m < 4; m++) ffma2(acc[r][m], cb[r], wv[m]);
        }
        __syncthreads();
    }

    // store Wh + fused a_w dot products
    float2 a1v[4], a2v[4];
#pragma unroll
    for (int m = 0; m < 4; m++) {
        a1v[m] = *(const float2*)&aw[2 * lane + 64 * m];
        a2v[m] = *(const float2*)&aw[FD + 2 * lane + 64 * m];
    }
#pragma unroll
    for (int r = 0; r < 8; r++) {
        float s1 = 0.f, s2 = 0.f;
#pragma unroll
        for (int m = 0; m < 4; m++) {
            float2 v = unpack2(acc[r][m]);
            *(float2*)&g_Wh[(r0 + 8 * w + r) * FD + 2 * lane + 64 * m] = v;
            s1 += v.x * a1v[m].x + v.y * a1v[m].y;
            s2 += v.x * a2v[m].x + v.y * a2v[m].y;
        }
#pragma unroll
        for (int off = 16; off > 0; off >>= 1) {
            s1 += __shfl_xor_sync(0xffffffffu, s1, off);
            s2 += __shfl_xor_sync(0xffffffffu, s2, off);
        }
        if (lane == 0) {
            int row = r0 + 8 * w + r;
            float P = s1, Q = s2 + ab[0];
            g_P[row] = P; g_Q[row] = Q;
            g_E1[row] = expf(P);          g_E2[row] = expf(NSLOPE * P);
            g_F1[row] = expf(Q);          g_F2[row] = expf(NSLOPE * Q);
            g_D[row] = 0.f;
        }
    }
}

// =====================================================================
// K3: column sums D[b,j] + fp16 masks (R3-proven version)
// =====================================================================
__global__ __launch_bounds__(256) void k_colsum(const float* __restrict__ A) {
    const int b = blockIdx.y;
    const int j = blockIdx.x * 256 + threadIdx.x;
    const int ibase = blockIdx.z * 256;
    __shared__ float sP[256], sE1[256], sE2[256];
    sP [threadIdx.x] = g_P [b * NN + ibase + threadIdx.x];
    sE1[threadIdx.x] = g_E1[b * NN + ibase + threadIdx.x];
    sE2[threadIdx.x] = g_E2[b * NN + ibase + threadIdx.x];
    __syncthreads();
    const float Qj = g_Q[b * NN + j], F1j = g_F1[b * NN + j], F2j = g_F2[b * NN + j];
    const float* Ab = A + (size_t)(b * NN + ibase) * NN + j;
    float acc = 0.f;
#pragma unroll 4
    for (int ii = 0; ii < 256; ii++) {
        float a = Ab[(size_t)ii * NN];
        bool pos = (sP[ii] + Qj > 0.f);
        acc = fmaf(a, pos ? sE1[ii] * F1j : sE2[ii] * F2j, acc);
        size_t mi = (size_t)(b * NN + ibase + ii) * NN + j;
        g_M1[mi] = __float2half_rn(pos ? a : 0.f);
        g_M2[mi] = __float2half_rn(pos ? 0.f : a);
    }
    atomicAdd(&g_D[b * NN + j], acc);
}

// =====================================================================
// K_hprep: H1 = (F1/D)*Wh, H2 = (F2/D)*Wh in fp16
// =====================================================================
__global__ __launch_bounds__(256) void k_hprep() {
    int e4 = blockIdx.x * 256 + threadIdx.x;
    int row = e4 >> 6;
    float inv = 1.f / (g_D[row] + EPSV);
    float r1 = g_F1[row] * inv, r2 = g_F2[row] * inv;
    float4 w = ((const float4*)g_Wh)[e4];
    __half2* h1 = (__half2*)g_H1;
    __half2* h2 = (__half2*)g_H2;
    h1[e4 * 2]     = __floats2half2_rn(w.x * r1, w.y * r1);
    h1[e4 * 2 + 1] = __floats2half2_rn(w.z * r1, w.w * r1);
    h2[e4 * 2]     = __floats2half2_rn(w.x * r2, w.y * r2);
    h2[e4 * 2 + 1] = __floats2half2_rn(w.z * r2, w.w * r2);
}

// =====================================================================
// K4: HMMA mask-GEMM, 4-deep cp.async pipeline, 1 sync/stage.
// Block 128i x 64o; stage = 32 j. Stage SMEM (24576B): M1 8K|M2 8K|B1 4K|B2 4K.
// 4 stages = 96 KB dynamic SMEM.
// =====================================================================
#define STG_STRIDE 24576

__device__ __forceinline__ uint32_t m_off(int i, int cq) {
    return (uint32_t)(((i >> 1) << 7) + (((((i & 1) << 2) | cq) ^ ((i >> 1) & 7)) << 4));
}
__device__ __forceinline__ uint32_t b_off(int j, int oc) {
    return (uint32_t)((j << 7) + (((oc ^ (j & 7))) << 4));
}

__global__ __launch_bounds__(256) void k_mma(float* __restrict__ out) {
    extern __shared__ __align__(128) char smem[];
    const uint32_t sb = smem_u32(smem);
    const int tid = threadIdx.x, lane = tid & 31, wid = tid >> 5;
    const int b = blockIdx.z;
    const int i0 = blockIdx.x * 128;
    const int o0 = blockIdx.y * 64;
    const int isub = (wid & 3) * 32;
    const int ocb = (wid >> 2) * 4;

    float acc[2][2][4][4];
#pragma unroll
    for (int t = 0; t < 2; t++)
#pragma unroll
        for (int m = 0; m < 2; m++)
#pragma unroll
            for (int n = 0; n < 4; n++)
#pragma unroll
                for (int k = 0; k < 4; k++) acc[t][m][n][k] = 0.f;

    auto issue = [&](int t) {
        const int j0 = t * 32;
        uint32_t stg = sb + (t & 3) * STG_STRIDE;
#pragma unroll
        for (int r = 0; r < 4; r++) {
            int idx = tid + 256 * r;
            int tens = idx >> 9, rem = idx & 511;
            int i = rem >> 2, cq = rem & 3;
            const __half* src = (tens ? g_M2 : g_M1) +
                ((size_t)(b * NN + i0 + i) * NN + j0 + cq * 8);
            cp_async16(stg + tens * 8192 + m_off(i, cq), src);
        }
#pragma unroll
        for (int r = 0; r < 2; r++) {
            int idx = tid + 256 * r;
            int tens = idx >> 8, rem = idx & 255;
            int j = rem >> 3, oc = rem & 7;
            const __half* src = (tens ? g_H2 : g_H1) +
                ((size_t)(b * NN + j0 + j) * FD + o0 + oc * 8);
            cp_async16(stg + 16384 + tens * 4096 + b_off(j, oc), src);
        }
        CP_COMMIT();
    };

    issue(0); issue(1); issue(2);

    for (int t = 0; t < 64; t++) {
        if (t <= 61)      { asm volatile("cp.async.wait_group 2;" ::: "memory"); }
        else if (t == 62) { asm volatile("cp.async.wait_group 1;" ::: "memory"); }
        else              { asm volatile("cp.async.wait_group 0;" ::: "memory"); }
        __syncthreads();

        uint32_t stg = sb + (t & 3) * STG_STRIDE;
#pragma unroll
        for (int tens = 0; tens < 2; tens++) {
            uint32_t Bf[4][4];
            uint32_t bb = stg + 16384 + tens * 4096;
#pragma unroll
            for (int jb = 0; jb < 4; jb++) {
                int oblk = lane >> 3;
                int j = jb * 8 + (lane & 7);
                uint32_t addr = bb + b_off(j, ocb + oblk);
                ldsm_x4_t(Bf[jb][0], Bf[jb][1], Bf[jb][2], Bf[jb][3], addr);
            }
            uint32_t mb = stg + tens * 8192;
#pragma unroll
            for (int m = 0; m < 2; m++) {
#pragma unroll
                for (int kt = 0; kt < 2; kt++) {
                    int q = lane >> 3;
                    int i = isub + m * 16 + ((q & 1) << 3) + (lane & 7);
                    int cq = (kt << 1) + (q >> 1);
                    uint32_t a[4];
                    ldsm_x4(a[0], a[1], a[2], a[3], mb + m_off(i, cq));
#pragma unroll
                    for (int nt = 0; nt < 4; nt++)
                        mma16816(acc[tens][m][nt], a, Bf[2 * kt][nt], Bf[2 * kt + 1][nt]);
                }
            }
        }
        if (t + 3 < 64) issue(t + 3);
    }

    // ---- epilogue: out = E1*D1 + E2*D2 ----
    const int gid = lane >> 2, t4 = lane & 3;
#pragma unroll
    for (int m = 0; m < 2; m++) {
        int r0 = i0 + isub + m * 16 + gid;
        int r1 = r0 + 8;
        float e1a = g_E1[b * NN + r0], e2a = g_E2[b * NN + r0];
        float e1b = g_E1[b * NN + r1], e2b = g_E2[b * NN + r1];
#pragma unroll
        for (int nt = 0; nt < 4; nt++) {
            int o = o0 + ocb * 8 + nt * 8 + 2 * t4;
            float2 v0, v1;
            v0.x = e1a * acc[0][m][nt][0] + e2a * acc[1][m][nt][0];
            v0.y = e1a * acc[0][m][nt][1] + e2a * acc[1][m][nt][1];
            v1.x = e1b * acc[0][m][nt][2] + e2b * acc[1][m][nt][2];
            v1.y = e1b * acc[0][m][nt][3] + e2b * acc[1][m][nt][3];
            *(float2*)&out[(size_t)(b * NN + r0) * FD + o] = v0;
            *(float2*)&out[(size_t)(b * NN + r1) * FD + o] = v1;
        }
    }
}

// =====================================================================
extern "C" void kernel_launch(void* const* d_in, const int* in_sizes, int n_in,
                              void* d_out, int out_size) {
    (void)in_sizes; (void)n_in; (void)out_size;
    const float* A  = (const float*)d_in[0];
    const float* x  = (const float*)d_in[1];
    const float* W  = (const float*)d_in[2];
    const float* aw = (const float*)d_in[3];
    const float* ab = (const float*)d_in[4];
    float* out = (float*)d_out;

    cudaFuncSetAttribute(k_mma, cudaFuncAttributeMaxDynamicSharedMemorySize,
                         4 * STG_STRIDE);

    k_gemm_wh<<<(BATCH * NN) / 64, 256>>>(x, W, aw, ab);
    k_colsum<<<dim3(NN / 256, BATCH, NN / 256), 256>>>(A);
    k_hprep<<<(BATCH * NN * FD) / 1024, 256>>>();
    k_mma<<<dim3(NN / 128, FD / 64, BATCH), 256, 4 * STG_STRIDE>>>(out);
}